// round 1
// baseline (speedup 1.0000x reference)
#include <cuda_runtime.h>
#include <cuda_bf16.h>

// Problem constants (validated against in_sizes at runtime by construction)
#define NMAX 50000
#define HD   128            // hidden dim
#define BM   64             // rows per GEMM block
#define GEMM_THREADS 256
#define AS_STRIDE4 33       // padded row stride in float4 (132 floats)

// Scratch (no allocation allowed; __device__ globals)
__device__ float g_m  [NMAX * HD];
__device__ float g_agg[NMAX * HD];
__device__ float g_h1 [NMAX * HD];
__device__ int   g_rs [NMAX + 1];

// ---------------------------------------------------------------------------
// GEMM: out[row][c] = sum_k A[gather(row)][k] * W[k][c] (+bias) (+=out) (relu)
// W (128x128) fully resident in smem; A tile 64x128 padded.
// ---------------------------------------------------------------------------
template<bool GATHER, bool RELU, bool ACCUM>
__global__ __launch_bounds__(GEMM_THREADS, 2)
void gemm128(const float* __restrict__ A, const int* __restrict__ gidx,
             const float* __restrict__ W, const float* __restrict__ bias,
             float* __restrict__ out, int nrows)
{
    extern __shared__ float smem[];
    float* Ws = smem;                 // 128*128 floats = 64KB
    float* As = smem + HD * HD;       // 64 rows * 132 floats

    const int tid  = threadIdx.x;
    const int row0 = blockIdx.x * BM;

    // Load W: 4096 float4, 16 per thread
    {
        const float4* W4  = (const float4*)W;
        float4*       Ws4 = (float4*)Ws;
        #pragma unroll
        for (int i = 0; i < 16; i++)
            Ws4[i * GEMM_THREADS + tid] = W4[i * GEMM_THREADS + tid];
    }

    // Load A tile (64 rows x 32 float4), row-major padded
    {
        float4* As4 = (float4*)As;
        #pragma unroll
        for (int i = 0; i < 8; i++) {
            int idx = i * GEMM_THREADS + tid;   // 0..2047
            int r   = idx >> 5;                 // 0..63
            int c4  = idx & 31;                 // 0..31
            float4 v = make_float4(0.f, 0.f, 0.f, 0.f);
            int grow = row0 + r;
            if (grow < nrows) {
                int arow = GATHER ? __ldg(&gidx[grow]) : grow;
                v = ((const float4*)A)[arow * 32 + c4];
            }
            As4[r * AS_STRIDE4 + c4] = v;
        }
    }
    __syncthreads();

    const int tx = tid & 31;    // column group: cols 4*tx .. 4*tx+3
    const int ty = tid >> 5;    // row group
    const int r0 = ty * 8;      // 8 rows per thread

    float acc[8][4];
    #pragma unroll
    for (int r = 0; r < 8; r++)
        #pragma unroll
        for (int c = 0; c < 4; c++) acc[r][c] = 0.f;

    const float4* Ws4 = (const float4*)Ws;
    const float4* As4 = (const float4*)As;

    #pragma unroll 4
    for (int k4 = 0; k4 < 32; k4++) {
        float4 w0 = Ws4[(k4 * 4 + 0) * 32 + tx];
        float4 w1 = Ws4[(k4 * 4 + 1) * 32 + tx];
        float4 w2 = Ws4[(k4 * 4 + 2) * 32 + tx];
        float4 w3 = Ws4[(k4 * 4 + 3) * 32 + tx];
        #pragma unroll
        for (int r = 0; r < 8; r++) {
            float4 a = As4[(r0 + r) * AS_STRIDE4 + k4];   // warp-broadcast
            acc[r][0] += a.x * w0.x + a.y * w1.x + a.z * w2.x + a.w * w3.x;
            acc[r][1] += a.x * w0.y + a.y * w1.y + a.z * w2.y + a.w * w3.y;
            acc[r][2] += a.x * w0.z + a.y * w1.z + a.z * w2.z + a.w * w3.z;
            acc[r][3] += a.x * w0.w + a.y * w1.w + a.z * w2.w + a.w * w3.w;
        }
    }

    float4 bv = make_float4(0.f, 0.f, 0.f, 0.f);
    if (bias) bv = ((const float4*)bias)[tx];

    #pragma unroll
    for (int r = 0; r < 8; r++) {
        int grow = row0 + r0 + r;
        if (grow < nrows) {
            float4 o;
            o.x = acc[r][0] + bv.x;
            o.y = acc[r][1] + bv.y;
            o.z = acc[r][2] + bv.z;
            o.w = acc[r][3] + bv.w;
            if (ACCUM) {
                float4 p = ((const float4*)out)[grow * 32 + tx];
                o.x += p.x; o.y += p.y; o.z += p.z; o.w += p.w;
            }
            if (RELU) {
                o.x = fmaxf(o.x, 0.f); o.y = fmaxf(o.y, 0.f);
                o.z = fmaxf(o.z, 0.f); o.w = fmaxf(o.w, 0.f);
            }
            ((float4*)out)[grow * 32 + tx] = o;
        }
    }
}

// ---------------------------------------------------------------------------
// CSR offsets from sorted dst: rs[n] = lower_bound(dst, n); rs[N] = E
// ---------------------------------------------------------------------------
__global__ void csr_offsets(const int* __restrict__ dst, int* __restrict__ rs,
                            int nE, int nN)
{
    int n = blockIdx.x * blockDim.x + threadIdx.x;
    if (n > nN) return;
    if (n == nN) { rs[n] = nE; return; }
    int lo = 0, hi = nE;
    while (lo < hi) {
        int mid = (lo + hi) >> 1;
        if (__ldg(&dst[mid]) < n) lo = mid + 1; else hi = mid;
    }
    rs[n] = lo;
}

// ---------------------------------------------------------------------------
// Segmented max over edges: one warp per dst node.
// Messages are relu outputs (>= 0), so 0-init reproduces the neginf->0 rule.
// ---------------------------------------------------------------------------
__global__ __launch_bounds__(256)
void seg_max(const float* __restrict__ m, const int* __restrict__ src,
             const int* __restrict__ rs, float* __restrict__ agg, int nN)
{
    int warp = (blockIdx.x * blockDim.x + threadIdx.x) >> 5;
    int lane = threadIdx.x & 31;
    if (warp >= nN) return;

    int e0 = __ldg(&rs[warp]);
    int e1 = __ldg(&rs[warp + 1]);

    float4 acc = make_float4(0.f, 0.f, 0.f, 0.f);
    for (int eb = e0; eb < e1; eb += 32) {
        int cnt = min(32, e1 - eb);
        int s_l = (lane < cnt) ? __ldg(&src[eb + lane]) : 0;
        for (int i = 0; i < cnt; i++) {
            int s = __shfl_sync(0xffffffffu, s_l, i);
            float4 v = ((const float4*)m)[s * 32 + lane];
            acc.x = fmaxf(acc.x, v.x);
            acc.y = fmaxf(acc.y, v.y);
            acc.z = fmaxf(acc.z, v.z);
            acc.w = fmaxf(acc.w, v.w);
        }
    }
    ((float4*)agg)[warp * 32 + lane] = acc;
}

// ---------------------------------------------------------------------------
// Launch
// ---------------------------------------------------------------------------
extern "C" void kernel_launch(void* const* d_in, const int* in_sizes, int n_in,
                              void* d_out, int out_size)
{
    const int*   node_ids = (const int*)  d_in[0];
    const int*   src      = (const int*)  d_in[1];
    const int*   dst      = (const int*)  d_in[2];
    const float* emb      = (const float*)d_in[3];
    const float* W_pool1  = (const float*)d_in[4];
    const float* b_pool1  = (const float*)d_in[5];
    const float* W_self1  = (const float*)d_in[6];
    const float* W_neigh1 = (const float*)d_in[7];
    const float* b1       = (const float*)d_in[8];
    const float* W_pool2  = (const float*)d_in[9];
    const float* b_pool2  = (const float*)d_in[10];
    const float* W_self2  = (const float*)d_in[11];
    const float* W_neigh2 = (const float*)d_in[12];
    const float* b2       = (const float*)d_in[13];
    float*       out      = (float*)d_out;

    const int nN = in_sizes[0];
    const int nE = in_sizes[1];

    float *m, *agg, *h1;
    int   *rs;
    cudaGetSymbolAddress((void**)&m,   g_m);
    cudaGetSymbolAddress((void**)&agg, g_agg);
    cudaGetSymbolAddress((void**)&h1,  g_h1);
    cudaGetSymbolAddress((void**)&rs,  g_rs);

    const int SMEM = (HD * HD + BM * AS_STRIDE4 * 4) * (int)sizeof(float);

    cudaFuncSetAttribute(gemm128<true,  true,  false>, cudaFuncAttributeMaxDynamicSharedMemorySize, SMEM);
    cudaFuncSetAttribute(gemm128<true,  false, false>, cudaFuncAttributeMaxDynamicSharedMemorySize, SMEM);
    cudaFuncSetAttribute(gemm128<false, true,  false>, cudaFuncAttributeMaxDynamicSharedMemorySize, SMEM);
    cudaFuncSetAttribute(gemm128<false, false, false>, cudaFuncAttributeMaxDynamicSharedMemorySize, SMEM);
    cudaFuncSetAttribute(gemm128<false, false, true >, cudaFuncAttributeMaxDynamicSharedMemorySize, SMEM);

    const int gemm_blocks = (nN + BM - 1) / BM;
    const int csr_blocks  = (nN + 1 + 255) / 256;
    const int seg_blocks  = (nN + 7) / 8;     // 8 warps/block, 1 warp/node

    // CSR offsets (same every call; recompute for determinism/graph rules)
    csr_offsets<<<csr_blocks, 256>>>(dst, rs, nE, nN);

    // ---- Layer 1 ----
    // m = relu(emb[node_ids] @ W_pool1 + b_pool1)
    gemm128<true, true, false><<<gemm_blocks, GEMM_THREADS, SMEM>>>(emb, node_ids, W_pool1, b_pool1, m, nN);
    // agg = segment_max(m[src], dst)
    seg_max<<<seg_blocks, 256>>>(m, src, rs, agg, nN);
    // h1 = emb[node_ids] @ W_self1 + b1
    gemm128<true, false, false><<<gemm_blocks, GEMM_THREADS, SMEM>>>(emb, node_ids, W_self1, b1, h1, nN);
    // h1 += agg @ W_neigh1
    gemm128<false, false, true><<<gemm_blocks, GEMM_THREADS, SMEM>>>(agg, nullptr, W_neigh1, nullptr, h1, nN);

    // ---- Layer 2 ----
    // m = relu(h1 @ W_pool2 + b_pool2)
    gemm128<false, true, false><<<gemm_blocks, GEMM_THREADS, SMEM>>>(h1, nullptr, W_pool2, b_pool2, m, nN);
    // agg = segment_max(m[src], dst)
    seg_max<<<seg_blocks, 256>>>(m, src, rs, agg, nN);
    // out = h1 @ W_self2 + b2
    gemm128<false, false, false><<<gemm_blocks, GEMM_THREADS, SMEM>>>(h1, nullptr, W_self2, b2, out, nN);
    // out += agg @ W_neigh2
    gemm128<false, false, true><<<gemm_blocks, GEMM_THREADS, SMEM>>>(agg, nullptr, W_neigh2, nullptr, out, nN);
}

// round 2
// speedup vs baseline: 1.6501x; 1.6501x over previous
#include <cuda_runtime.h>
#include <cuda_bf16.h>
#include <cstdint>

#define NMAX 50000
#define HD   128
#define BM   64
#define GEMM_THREADS 256
#define AS_W 132        // A smem row stride (floats): 132 % 32 == 4 -> A frag conflict-free
#define WS_W 136        // W smem row stride (floats): 136 % 32 == 8 -> B frag conflict-free

__device__ float g_m  [NMAX * HD];
__device__ float g_agg[NMAX * HD];
__device__ float g_h1 [NMAX * HD];
__device__ int   g_rs [NMAX + 1];

__device__ __forceinline__ uint32_t f2tf32(float x) {
    uint32_t r;
    asm("cvt.rna.tf32.f32 %0, %1;" : "=r"(r) : "f"(x));
    return r;
}

__device__ __forceinline__ void mma_tf32(float c[4], const uint32_t a[4], const uint32_t b[2]) {
    asm volatile(
        "mma.sync.aligned.m16n8k8.row.col.f32.tf32.tf32.f32 "
        "{%0,%1,%2,%3}, {%4,%5,%6,%7}, {%8,%9}, {%0,%1,%2,%3};"
        : "+f"(c[0]), "+f"(c[1]), "+f"(c[2]), "+f"(c[3])
        : "r"(a[0]), "r"(a[1]), "r"(a[2]), "r"(a[3]), "r"(b[0]), "r"(b[1]));
}

// ---------------------------------------------------------------------------
// TF32 tensor-core GEMM: out[row][:] = A[gather(row)][:] @ W (+bias)(+out)(relu)
// BM=64 rows per CTA, N=128, K=128 fully smem-resident.
// ---------------------------------------------------------------------------
template<bool GATHER, bool RELU, bool ACCUM>
__global__ __launch_bounds__(GEMM_THREADS, 2)
void gemm_tc(const float* __restrict__ A, const int* __restrict__ gidx,
             const float* __restrict__ W, const float* __restrict__ bias,
             float* __restrict__ out, int nrows)
{
    extern __shared__ float smem[];
    float* As = smem;                       // 64 * 132
    float* Ws = smem + BM * AS_W;           // 128 * 136

    const int tid  = threadIdx.x;
    const int row0 = blockIdx.x * BM;

    // ---- Stage W (128x128) into smem as tf32 bits, padded stride 136 ----
    {
        const float4* W4 = (const float4*)W;
        #pragma unroll
        for (int i = 0; i < 16; i++) {
            int idx = i * GEMM_THREADS + tid;      // 0..4095 float4s
            int k   = idx >> 5;
            int c4  = idx & 31;
            float4 v = W4[idx];
            float4 t;
            t.x = __uint_as_float(f2tf32(v.x));
            t.y = __uint_as_float(f2tf32(v.y));
            t.z = __uint_as_float(f2tf32(v.z));
            t.w = __uint_as_float(f2tf32(v.w));
            *(float4*)&Ws[k * WS_W + c4 * 4] = t;
        }
    }

    // ---- Stage A tile (64x128) into smem as tf32 bits, padded stride 132 ----
    {
        #pragma unroll
        for (int i = 0; i < 8; i++) {
            int idx = i * GEMM_THREADS + tid;      // 0..2047 float4s
            int r   = idx >> 5;
            int c4  = idx & 31;
            float4 v = make_float4(0.f, 0.f, 0.f, 0.f);
            int grow = row0 + r;
            if (grow < nrows) {
                int arow = GATHER ? __ldg(&gidx[grow]) : grow;
                v = ((const float4*)A)[arow * 32 + c4];
            }
            float4 t;
            t.x = __uint_as_float(f2tf32(v.x));
            t.y = __uint_as_float(f2tf32(v.y));
            t.z = __uint_as_float(f2tf32(v.z));
            t.w = __uint_as_float(f2tf32(v.w));
            *(float4*)&As[r * AS_W + c4 * 4] = t;
        }
    }
    __syncthreads();

    const int lane = tid & 31;
    const int wid  = tid >> 5;
    const int wm   = wid & 1;        // 2 warp-rows of 32
    const int wn   = wid >> 1;       // 4 warp-cols of 32
    const int g    = lane >> 2;      // 0..7
    const int tg   = lane & 3;       // 0..3

    float acc[2][4][4];
    #pragma unroll
    for (int mt = 0; mt < 2; mt++)
        #pragma unroll
        for (int nt = 0; nt < 4; nt++)
            #pragma unroll
            for (int i = 0; i < 4; i++) acc[mt][nt][i] = 0.f;

    #pragma unroll
    for (int ks = 0; ks < 16; ks++) {
        const int k0 = ks * 8;

        uint32_t a[2][4];
        #pragma unroll
        for (int mt = 0; mt < 2; mt++) {
            const float* ap = &As[(wm * 32 + mt * 16 + g) * AS_W + k0 + tg];
            a[mt][0] = __float_as_uint(ap[0]);
            a[mt][1] = __float_as_uint(ap[8 * AS_W]);
            a[mt][2] = __float_as_uint(ap[4]);
            a[mt][3] = __float_as_uint(ap[8 * AS_W + 4]);
        }

        uint32_t b[4][2];
        #pragma unroll
        for (int nt = 0; nt < 4; nt++) {
            const float* bp = &Ws[(k0 + tg) * WS_W + wn * 32 + nt * 8 + g];
            b[nt][0] = __float_as_uint(bp[0]);
            b[nt][1] = __float_as_uint(bp[4 * WS_W]);
        }

        #pragma unroll
        for (int mt = 0; mt < 2; mt++)
            #pragma unroll
            for (int nt = 0; nt < 4; nt++)
                mma_tf32(acc[mt][nt], a[mt], b[nt]);
    }

    // ---- Epilogue ----
    #pragma unroll
    for (int mt = 0; mt < 2; mt++) {
        int r_lo = row0 + wm * 32 + mt * 16 + g;      // rows r_lo, r_lo+8
        #pragma unroll
        for (int half = 0; half < 2; half++) {
            int grow = r_lo + half * 8;
            if (grow >= nrows) continue;
            #pragma unroll
            for (int nt = 0; nt < 4; nt++) {
                int col = wn * 32 + nt * 8 + 2 * tg;
                float2 o;
                o.x = acc[mt][nt][half * 2 + 0];
                o.y = acc[mt][nt][half * 2 + 1];
                if (bias) {
                    float2 bv = *(const float2*)(bias + col);
                    o.x += bv.x; o.y += bv.y;
                }
                if (ACCUM) {
                    float2 p = *(const float2*)(out + grow * HD + col);
                    o.x += p.x; o.y += p.y;
                }
                if (RELU) { o.x = fmaxf(o.x, 0.f); o.y = fmaxf(o.y, 0.f); }
                *(float2*)(out + grow * HD + col) = o;
            }
        }
    }
}

// ---------------------------------------------------------------------------
// CSR offsets from sorted dst
// ---------------------------------------------------------------------------
__global__ void csr_offsets(const int* __restrict__ dst, int* __restrict__ rs,
                            int nE, int nN)
{
    int n = blockIdx.x * blockDim.x + threadIdx.x;
    if (n > nN) return;
    if (n == nN) { rs[n] = nE; return; }
    int lo = 0, hi = nE;
    while (lo < hi) {
        int mid = (lo + hi) >> 1;
        if (__ldg(&dst[mid]) < n) lo = mid + 1; else hi = mid;
    }
    rs[n] = lo;
}

// ---------------------------------------------------------------------------
// Segmented max (messages >= 0 so 0-init matches DGL neginf->0 rule)
// ---------------------------------------------------------------------------
__global__ __launch_bounds__(256)
void seg_max(const float* __restrict__ m, const int* __restrict__ src,
             const int* __restrict__ rs, float* __restrict__ agg, int nN)
{
    int warp = (blockIdx.x * blockDim.x + threadIdx.x) >> 5;
    int lane = threadIdx.x & 31;
    if (warp >= nN) return;

    int e0 = __ldg(&rs[warp]);
    int e1 = __ldg(&rs[warp + 1]);

    float4 acc = make_float4(0.f, 0.f, 0.f, 0.f);
    for (int eb = e0; eb < e1; eb += 32) {
        int cnt = min(32, e1 - eb);
        int s_l = (lane < cnt) ? __ldg(&src[eb + lane]) : 0;
        for (int i = 0; i < cnt; i++) {
            int s = __shfl_sync(0xffffffffu, s_l, i);
            float4 v = ((const float4*)m)[s * 32 + lane];
            acc.x = fmaxf(acc.x, v.x);
            acc.y = fmaxf(acc.y, v.y);
            acc.z = fmaxf(acc.z, v.z);
            acc.w = fmaxf(acc.w, v.w);
        }
    }
    ((float4*)agg)[warp * 32 + lane] = acc;
}

// ---------------------------------------------------------------------------
extern "C" void kernel_launch(void* const* d_in, const int* in_sizes, int n_in,
                              void* d_out, int out_size)
{
    const int*   node_ids = (const int*)  d_in[0];
    const int*   src      = (const int*)  d_in[1];
    const int*   dst      = (const int*)  d_in[2];
    const float* emb      = (const float*)d_in[3];
    const float* W_pool1  = (const float*)d_in[4];
    const float* b_pool1  = (const float*)d_in[5];
    const float* W_self1  = (const float*)d_in[6];
    const float* W_neigh1 = (const float*)d_in[7];
    const float* b1       = (const float*)d_in[8];
    const float* W_pool2  = (const float*)d_in[9];
    const float* b_pool2  = (const float*)d_in[10];
    const float* W_self2  = (const float*)d_in[11];
    const float* W_neigh2 = (const float*)d_in[12];
    const float* b2       = (const float*)d_in[13];
    float*       out      = (float*)d_out;

    const int nN = in_sizes[0];
    const int nE = in_sizes[1];

    float *m, *agg, *h1;
    int   *rs;
    cudaGetSymbolAddress((void**)&m,   g_m);
    cudaGetSymbolAddress((void**)&agg, g_agg);
    cudaGetSymbolAddress((void**)&h1,  g_h1);
    cudaGetSymbolAddress((void**)&rs,  g_rs);

    const int SMEM = (BM * AS_W + HD * WS_W) * (int)sizeof(float);

    cudaFuncSetAttribute(gemm_tc<true,  true,  false>, cudaFuncAttributeMaxDynamicSharedMemorySize, SMEM);
    cudaFuncSetAttribute(gemm_tc<true,  false, false>, cudaFuncAttributeMaxDynamicSharedMemorySize, SMEM);
    cudaFuncSetAttribute(gemm_tc<false, true,  false>, cudaFuncAttributeMaxDynamicSharedMemorySize, SMEM);
    cudaFuncSetAttribute(gemm_tc<false, false, false>, cudaFuncAttributeMaxDynamicSharedMemorySize, SMEM);
    cudaFuncSetAttribute(gemm_tc<false, false, true >, cudaFuncAttributeMaxDynamicSharedMemorySize, SMEM);

    const int gemm_blocks = (nN + BM - 1) / BM;
    const int csr_blocks  = (nN + 1 + 255) / 256;
    const int seg_blocks  = (nN + 7) / 8;

    csr_offsets<<<csr_blocks, 256>>>(dst, rs, nE, nN);

    // ---- Layer 1 ----
    gemm_tc<true, true, false><<<gemm_blocks, GEMM_THREADS, SMEM>>>(emb, node_ids, W_pool1, b_pool1, m, nN);
    seg_max<<<seg_blocks, 256>>>(m, src, rs, agg, nN);
    gemm_tc<true, false, false><<<gemm_blocks, GEMM_THREADS, SMEM>>>(emb, node_ids, W_self1, b1, h1, nN);
    gemm_tc<false, false, true><<<gemm_blocks, GEMM_THREADS, SMEM>>>(agg, nullptr, W_neigh1, nullptr, h1, nN);

    // ---- Layer 2 ----
    gemm_tc<false, true, false><<<gemm_blocks, GEMM_THREADS, SMEM>>>(h1, nullptr, W_pool2, b_pool2, m, nN);
    seg_max<<<seg_blocks, 256>>>(m, src, rs, agg, nN);
    gemm_tc<false, false, false><<<gemm_blocks, GEMM_THREADS, SMEM>>>(h1, nullptr, W_self2, b2, out, nN);
    gemm_tc<false, false, true><<<gemm_blocks, GEMM_THREADS, SMEM>>>(agg, nullptr, W_neigh2, nullptr, out, nN);
}

// round 3
// speedup vs baseline: 1.9516x; 1.1827x over previous
#include <cuda_runtime.h>
#include <cuda_fp16.h>
#include <cstdint>

#define NMAX 50000
#define HD   128
#define BM   128
#define GEMM_THREADS 256
#define SLICE 1028                 // words per k-slice: 128*8 + 4 pad
#define WORDS (16 * SLICE)         // 16448 words per A-tile / per W

__device__ float  g_wp [6][WORDS];       // pre-permuted tf32 weights
__device__ __half g_mh [NMAX * HD];      // pool messages (fp16)
__device__ float  g_agg[NMAX * HD];
__device__ float  g_h1 [NMAX * HD];
__device__ int    g_rs [NMAX + 1];

__device__ __forceinline__ uint32_t f2tf32(float x) {
    uint32_t r;
    asm("cvt.rna.tf32.f32 %0, %1;" : "=r"(r) : "f"(x));
    return r;
}

__device__ __forceinline__ void mma_tf32(float c[4], uint32_t a0, uint32_t a1,
                                         uint32_t a2, uint32_t a3,
                                         uint32_t b0, uint32_t b1) {
    asm volatile(
        "mma.sync.aligned.m16n8k8.row.col.f32.tf32.tf32.f32 "
        "{%0,%1,%2,%3}, {%4,%5,%6,%7}, {%8,%9}, {%0,%1,%2,%3};"
        : "+f"(c[0]), "+f"(c[1]), "+f"(c[2]), "+f"(c[3])
        : "r"(a0), "r"(a1), "r"(a2), "r"(a3), "r"(b0), "r"(b1));
}

// ---------------------------------------------------------------------------
// Weight prep: convert fp32 W[k][col] -> tf32, permuted fragment layout:
// word(k,col) = ks*SLICE + col*8 + tg*2 + h   (k = ks*8 + tg + 4h)
// ---------------------------------------------------------------------------
__global__ void prep_w(const float* w0, const float* w1, const float* w2,
                       const float* w3, const float* w4, const float* w5)
{
    const float* W;
    switch (blockIdx.y) {
        case 0: W = w0; break; case 1: W = w1; break; case 2: W = w2; break;
        case 3: W = w3; break; case 4: W = w4; break; default: W = w5; break;
    }
    int t = blockIdx.x * blockDim.x + threadIdx.x;     // 0..8191
    int ks  = t >> 9;
    int col = (t >> 2) & 127;
    int tg  = t & 3;
    float2 o;
    o.x = __uint_as_float(f2tf32(W[(ks * 8 + tg    ) * HD + col]));
    o.y = __uint_as_float(f2tf32(W[(ks * 8 + tg + 4) * HD + col]));
    *(float2*)&g_wp[blockIdx.y][ks * SLICE + col * 8 + tg * 2] = o;
}

// ---------------------------------------------------------------------------
// Stage A tile (BM x 128) into fragment-layout smem (tf32 bits)
// ---------------------------------------------------------------------------
template<bool GATHER>
__device__ __forceinline__ void stage_A(const float* __restrict__ A,
                                        const int* __restrict__ gidx,
                                        int row0, int nrows, float* As)
{
    const int tid = threadIdx.x;
    #pragma unroll
    for (int i = 0; i < 8; i++) {
        int idx = i * GEMM_THREADS + tid;   // 0..2047
        int r   = idx >> 4;                 // 0..127
        int ks  = idx & 15;
        float4 v0 = make_float4(0.f,0.f,0.f,0.f);
        float4 v1 = v0;
        int grow = row0 + r;
        if (grow < nrows) {
            int arow = GATHER ? __ldg(&gidx[grow]) : grow;
            const float4* rp = (const float4*)(A + (size_t)arow * HD);
            v0 = rp[2 * ks];
            v1 = rp[2 * ks + 1];
        }
        float* d = As + ks * SLICE + r * 8;
        float4 s0, s1;
        s0.x = __uint_as_float(f2tf32(v0.x)); s0.y = __uint_as_float(f2tf32(v1.x));
        s0.z = __uint_as_float(f2tf32(v0.y)); s0.w = __uint_as_float(f2tf32(v1.y));
        s1.x = __uint_as_float(f2tf32(v0.z)); s1.y = __uint_as_float(f2tf32(v1.z));
        s1.z = __uint_as_float(f2tf32(v0.w)); s1.w = __uint_as_float(f2tf32(v1.w));
        *(float4*)(d)     = s0;
        *(float4*)(d + 4) = s1;
    }
}

// ---------------------------------------------------------------------------
// Fused dual-W GEMM: m = relu(A@W0 + b0) (fp16), self = A@W1 + b1 (fp32)
// ---------------------------------------------------------------------------
template<bool GATHER>
__global__ __launch_bounds__(GEMM_THREADS, 1)
void gemm_fused(const float* __restrict__ A, const int* __restrict__ gidx,
                int w0i, int w1i,
                const float* __restrict__ b0, const float* __restrict__ b1,
                __half* __restrict__ m_out, float* __restrict__ self_out,
                int nrows)
{
    extern __shared__ float smem[];
    float* As  = smem;
    float* Wp0 = smem + WORDS;
    float* Wp1 = smem + 2 * WORDS;

    const int tid  = threadIdx.x;
    const int row0 = blockIdx.x * BM;

    {   // copy pre-permuted weights
        const float4* s0 = (const float4*)g_wp[w0i];
        const float4* s1 = (const float4*)g_wp[w1i];
        float4* d0 = (float4*)Wp0;
        float4* d1 = (float4*)Wp1;
        #pragma unroll
        for (int i = 0; i < 17; i++) {
            int idx = i * GEMM_THREADS + tid;
            if (idx < WORDS / 4) { d0[idx] = s0[idx]; d1[idx] = s1[idx]; }
        }
    }
    stage_A<GATHER>(A, gidx, row0, nrows, As);
    __syncthreads();

    const int lane = tid & 31, wid = tid >> 5;
    const int wm = wid & 1, wn = wid >> 1;
    const int g = lane >> 2, tg = lane & 3;
    const int R = wm * 64;

    float acc0[4][4][4], acc1[4][4][4];
    #pragma unroll
    for (int mt = 0; mt < 4; mt++)
        #pragma unroll
        for (int nt = 0; nt < 4; nt++)
            #pragma unroll
            for (int i = 0; i < 4; i++) { acc0[mt][nt][i] = 0.f; acc1[mt][nt][i] = 0.f; }

    #pragma unroll
    for (int ks = 0; ks < 16; ks++) {
        const float* as = As + ks * SLICE;
        float2 afA[4], afB[4];
        #pragma unroll
        for (int mt = 0; mt < 4; mt++) {
            int r = R + mt * 16 + g;
            afA[mt] = *(const float2*)(as + r * 8 + tg * 2);
            afB[mt] = *(const float2*)(as + (r + 8) * 8 + tg * 2);
        }
        const float* ws0 = Wp0 + ks * SLICE;
        const float* ws1 = Wp1 + ks * SLICE;
        #pragma unroll
        for (int nt = 0; nt < 4; nt++) {
            int cw = (wn * 32 + nt * 8 + g) * 8 + tg * 2;
            float2 bf0 = *(const float2*)(ws0 + cw);
            float2 bf1 = *(const float2*)(ws1 + cw);
            #pragma unroll
            for (int mt = 0; mt < 4; mt++) {
                mma_tf32(acc0[mt][nt],
                         __float_as_uint(afA[mt].x), __float_as_uint(afB[mt].x),
                         __float_as_uint(afA[mt].y), __float_as_uint(afB[mt].y),
                         __float_as_uint(bf0.x), __float_as_uint(bf0.y));
                mma_tf32(acc1[mt][nt],
                         __float_as_uint(afA[mt].x), __float_as_uint(afB[mt].x),
                         __float_as_uint(afA[mt].y), __float_as_uint(afB[mt].y),
                         __float_as_uint(bf1.x), __float_as_uint(bf1.y));
            }
        }
    }

    // biases for this thread's columns
    float2 bv0[4], bv1[4];
    #pragma unroll
    for (int nt = 0; nt < 4; nt++) {
        int col = wn * 32 + nt * 8 + 2 * tg;
        bv0[nt] = *(const float2*)(b0 + col);
        bv1[nt] = *(const float2*)(b1 + col);
    }

    #pragma unroll
    for (int mt = 0; mt < 4; mt++) {
        #pragma unroll
        for (int hh = 0; hh < 2; hh++) {
            int grow = row0 + R + mt * 16 + g + hh * 8;
            if (grow >= nrows) continue;
            #pragma unroll
            for (int nt = 0; nt < 4; nt++) {
                int col = wn * 32 + nt * 8 + 2 * tg;
                float mx = fmaxf(acc0[mt][nt][hh*2+0] + bv0[nt].x, 0.f);
                float my = fmaxf(acc0[mt][nt][hh*2+1] + bv0[nt].y, 0.f);
                *(__half2*)(m_out + (size_t)grow * HD + col) =
                    __floats2half2_rn(mx, my);
                float2 s;
                s.x = acc1[mt][nt][hh*2+0] + bv1[nt].x;
                s.y = acc1[mt][nt][hh*2+1] + bv1[nt].y;
                *(float2*)(self_out + (size_t)grow * HD + col) = s;
            }
        }
    }
}

// ---------------------------------------------------------------------------
// Accumulate GEMM: out += A @ W
// ---------------------------------------------------------------------------
__global__ __launch_bounds__(GEMM_THREADS, 1)
void gemm_acc(const float* __restrict__ A, int wi, float* __restrict__ out,
              int nrows)
{
    extern __shared__ float smem[];
    float* As = smem;
    float* Wp = smem + WORDS;

    const int tid  = threadIdx.x;
    const int row0 = blockIdx.x * BM;

    {
        const float4* s = (const float4*)g_wp[wi];
        float4* d = (float4*)Wp;
        #pragma unroll
        for (int i = 0; i < 17; i++) {
            int idx = i * GEMM_THREADS + tid;
            if (idx < WORDS / 4) d[idx] = s[idx];
        }
    }
    stage_A<false>(A, nullptr, row0, nrows, As);
    __syncthreads();

    const int lane = tid & 31, wid = tid >> 5;
    const int wm = wid & 1, wn = wid >> 1;
    const int g = lane >> 2, tg = lane & 3;
    const int R = wm * 64;

    float acc[4][4][4];
    #pragma unroll
    for (int mt = 0; mt < 4; mt++)
        #pragma unroll
        for (int nt = 0; nt < 4; nt++)
            #pragma unroll
            for (int i = 0; i < 4; i++) acc[mt][nt][i] = 0.f;

    #pragma unroll
    for (int ks = 0; ks < 16; ks++) {
        const float* as = As + ks * SLICE;
        float2 afA[4], afB[4];
        #pragma unroll
        for (int mt = 0; mt < 4; mt++) {
            int r = R + mt * 16 + g;
            afA[mt] = *(const float2*)(as + r * 8 + tg * 2);
            afB[mt] = *(const float2*)(as + (r + 8) * 8 + tg * 2);
        }
        const float* ws = Wp + ks * SLICE;
        #pragma unroll
        for (int nt = 0; nt < 4; nt++) {
            int cw = (wn * 32 + nt * 8 + g) * 8 + tg * 2;
            float2 bf = *(const float2*)(ws + cw);
            #pragma unroll
            for (int mt = 0; mt < 4; mt++)
                mma_tf32(acc[mt][nt],
                         __float_as_uint(afA[mt].x), __float_as_uint(afB[mt].x),
                         __float_as_uint(afA[mt].y), __float_as_uint(afB[mt].y),
                         __float_as_uint(bf.x), __float_as_uint(bf.y));
        }
    }

    #pragma unroll
    for (int mt = 0; mt < 4; mt++) {
        #pragma unroll
        for (int hh = 0; hh < 2; hh++) {
            int grow = row0 + R + mt * 16 + g + hh * 8;
            if (grow >= nrows) continue;
            #pragma unroll
            for (int nt = 0; nt < 4; nt++) {
                int col = wn * 32 + nt * 8 + 2 * tg;
                float2 p = *(const float2*)(out + (size_t)grow * HD + col);
                p.x += acc[mt][nt][hh*2+0];
                p.y += acc[mt][nt][hh*2+1];
                *(float2*)(out + (size_t)grow * HD + col) = p;
            }
        }
    }
}

// ---------------------------------------------------------------------------
__global__ void csr_offsets(const int* __restrict__ dst, int* __restrict__ rs,
                            int nE, int nN)
{
    int n = blockIdx.x * blockDim.x + threadIdx.x;
    if (n > nN) return;
    if (n == nN) { rs[n] = nE; return; }
    int lo = 0, hi = nE;
    while (lo < hi) {
        int mid = (lo + hi) >> 1;
        if (__ldg(&dst[mid]) < n) lo = mid + 1; else hi = mid;
    }
    rs[n] = lo;
}

// ---------------------------------------------------------------------------
// Segmented max over fp16 messages (>=0, so 0-init matches neginf->0 rule)
// ---------------------------------------------------------------------------
__global__ __launch_bounds__(256)
void seg_max_h(const __half* __restrict__ m, const int* __restrict__ src,
               const int* __restrict__ rs, float* __restrict__ agg, int nN)
{
    int warp = (blockIdx.x * blockDim.x + threadIdx.x) >> 5;
    int lane = threadIdx.x & 31;
    if (warp >= nN) return;

    int e0 = __ldg(&rs[warp]);
    int e1 = __ldg(&rs[warp + 1]);

    const __half2 z = __float2half2_rn(0.f);
    __half2 a0 = z, a1 = z;
    const uint2* m2 = (const uint2*)m;   // 8 bytes = 4 halfs per lane

    for (int eb = e0; eb < e1; eb += 32) {
        int cnt = min(32, e1 - eb);
        int s_l = (lane < cnt) ? __ldg(&src[eb + lane]) : 0;
        for (int i = 0; i < cnt; i++) {
            int s = __shfl_sync(0xffffffffu, s_l, i);
            uint2 v = __ldg(&m2[(size_t)s * 32 + lane]);
            a0 = __hmax2(a0, *(__half2*)&v.x);
            a1 = __hmax2(a1, *(__half2*)&v.y);
        }
    }
    float2 f0 = __half22float2(a0);
    float2 f1 = __half22float2(a1);
    float4 o = make_float4(f0.x, f0.y, f1.x, f1.y);
    ((float4*)agg)[(size_t)warp * 32 + lane] = o;
}

// ---------------------------------------------------------------------------
extern "C" void kernel_launch(void* const* d_in, const int* in_sizes, int n_in,
                              void* d_out, int out_size)
{
    const int*   node_ids = (const int*)  d_in[0];
    const int*   src      = (const int*)  d_in[1];
    const int*   dst      = (const int*)  d_in[2];
    const float* emb      = (const float*)d_in[3];
    const float* W_pool1  = (const float*)d_in[4];
    const float* b_pool1  = (const float*)d_in[5];
    const float* W_self1  = (const float*)d_in[6];
    const float* W_neigh1 = (const float*)d_in[7];
    const float* b1       = (const float*)d_in[8];
    const float* W_pool2  = (const float*)d_in[9];
    const float* b_pool2  = (const float*)d_in[10];
    const float* W_self2  = (const float*)d_in[11];
    const float* W_neigh2 = (const float*)d_in[12];
    const float* b2       = (const float*)d_in[13];
    float*       out      = (float*)d_out;

    const int nN = in_sizes[0];
    const int nE = in_sizes[1];

    __half* mh;  float *agg, *h1;  int *rs;
    cudaGetSymbolAddress((void**)&mh,  g_mh);
    cudaGetSymbolAddress((void**)&agg, g_agg);
    cudaGetSymbolAddress((void**)&h1,  g_h1);
    cudaGetSymbolAddress((void**)&rs,  g_rs);

    const int SMEM3 = 3 * WORDS * (int)sizeof(float);   // 197376
    const int SMEM2 = 2 * WORDS * (int)sizeof(float);   // 131584

    cudaFuncSetAttribute(gemm_fused<true >, cudaFuncAttributeMaxDynamicSharedMemorySize, SMEM3);
    cudaFuncSetAttribute(gemm_fused<false>, cudaFuncAttributeMaxDynamicSharedMemorySize, SMEM3);
    cudaFuncSetAttribute(gemm_acc,          cudaFuncAttributeMaxDynamicSharedMemorySize, SMEM2);

    const int gemm_blocks = (nN + BM - 1) / BM;
    const int csr_blocks  = (nN + 1 + 255) / 256;
    const int seg_blocks  = (nN + 7) / 8;

    prep_w<<<dim3(32, 6), 256>>>(W_pool1, W_self1, W_neigh1, W_pool2, W_self2, W_neigh2);
    csr_offsets<<<csr_blocks, 256>>>(dst, rs, nE, nN);

    // ---- Layer 1 ----
    gemm_fused<true><<<gemm_blocks, GEMM_THREADS, SMEM3>>>(
        emb, node_ids, 0, 1, b_pool1, b1, mh, h1, nN);
    seg_max_h<<<seg_blocks, 256>>>(mh, src, rs, agg, nN);
    gemm_acc<<<gemm_blocks, GEMM_THREADS, SMEM2>>>(agg, 2, h1, nN);

    // ---- Layer 2 ----
    gemm_fused<false><<<gemm_blocks, GEMM_THREADS, SMEM3>>>(
        h1, nullptr, 3, 4, b_pool2, b2, mh, out, nN);
    seg_max_h<<<seg_blocks, 256>>>(mh, src, rs, agg, nN);
    gemm_acc<<<gemm_blocks, GEMM_THREADS, SMEM2>>>(agg, 5, out, nN);
}

// round 4
// speedup vs baseline: 2.0237x; 1.0369x over previous
#include <cuda_runtime.h>
#include <cuda_fp16.h>
#include <cstdint>

#define NMAX 50000
#define HD   128
#define BM   128
#define GT   512                   // GEMM threads (16 warps)
#define SLICE 1028                 // words per k-slice: 128*8 + 4 pad
#define WORDS (16 * SLICE)         // 16448 words per A-tile / per W

__device__ float  g_wp [6][WORDS];       // pre-permuted tf32 weights
__device__ __half g_mh [NMAX * HD];      // pool messages (fp16)
__device__ float  g_agg[NMAX * HD];
__device__ float  g_h1 [NMAX * HD];
__device__ int    g_rs [NMAX + 1];

__device__ __forceinline__ uint32_t f2tf32(float x) {
    uint32_t r;
    asm("cvt.rna.tf32.f32 %0, %1;" : "=r"(r) : "f"(x));
    return r;
}

__device__ __forceinline__ void mma_tf32(float c[4], uint32_t a0, uint32_t a1,
                                         uint32_t a2, uint32_t a3,
                                         uint32_t b0, uint32_t b1) {
    asm volatile(
        "mma.sync.aligned.m16n8k8.row.col.f32.tf32.tf32.f32 "
        "{%0,%1,%2,%3}, {%4,%5,%6,%7}, {%8,%9}, {%0,%1,%2,%3};"
        : "+f"(c[0]), "+f"(c[1]), "+f"(c[2]), "+f"(c[3])
        : "r"(a0), "r"(a1), "r"(a2), "r"(a3), "r"(b0), "r"(b1));
}

// ---------------------------------------------------------------------------
// Weight prep: fp32 W[k][col] -> tf32 fragment layout:
// word(k,col) = ks*SLICE + col*8 + tg*2 + h   (k = ks*8 + tg + 4h)
// ---------------------------------------------------------------------------
__global__ void prep_w(const float* w0, const float* w1, const float* w2,
                       const float* w3, const float* w4, const float* w5)
{
    const float* W;
    switch (blockIdx.y) {
        case 0: W = w0; break; case 1: W = w1; break; case 2: W = w2; break;
        case 3: W = w3; break; case 4: W = w4; break; default: W = w5; break;
    }
    int t = blockIdx.x * blockDim.x + threadIdx.x;     // 0..8191
    int ks  = t >> 9;
    int col = (t >> 2) & 127;
    int tg  = t & 3;
    float2 o;
    o.x = __uint_as_float(f2tf32(W[(ks * 8 + tg    ) * HD + col]));
    o.y = __uint_as_float(f2tf32(W[(ks * 8 + tg + 4) * HD + col]));
    *(float2*)&g_wp[blockIdx.y][ks * SLICE + col * 8 + tg * 2] = o;
}

// ---------------------------------------------------------------------------
// Stage A tile (BM x 128) into fragment-layout smem (tf32 bits). 512 threads.
// ---------------------------------------------------------------------------
template<bool GATHER>
__device__ __forceinline__ void stage_A(const float* __restrict__ A,
                                        const int* __restrict__ gidx,
                                        int row0, int nrows, float* As)
{
    const int tid = threadIdx.x;
    #pragma unroll
    for (int i = 0; i < 4; i++) {
        int idx = i * GT + tid;             // 0..2047
        int r   = idx >> 4;                 // 0..127
        int ks  = idx & 15;
        float4 v0 = make_float4(0.f,0.f,0.f,0.f);
        float4 v1 = v0;
        int grow = row0 + r;
        if (grow < nrows) {
            int arow = GATHER ? __ldg(&gidx[grow]) : grow;
            const float4* rp = (const float4*)(A + (size_t)arow * HD);
            v0 = rp[2 * ks];
            v1 = rp[2 * ks + 1];
        }
        float* d = As + ks * SLICE + r * 8;
        float4 s0, s1;
        s0.x = __uint_as_float(f2tf32(v0.x)); s0.y = __uint_as_float(f2tf32(v1.x));
        s0.z = __uint_as_float(f2tf32(v0.y)); s0.w = __uint_as_float(f2tf32(v1.y));
        s1.x = __uint_as_float(f2tf32(v0.z)); s1.y = __uint_as_float(f2tf32(v1.z));
        s1.z = __uint_as_float(f2tf32(v0.w)); s1.w = __uint_as_float(f2tf32(v1.w));
        *(float4*)(d)     = s0;
        *(float4*)(d + 4) = s1;
    }
}

// ---------------------------------------------------------------------------
// Fused dual-W GEMM: m = relu(A@W0 + b0) (fp16), self = A@W1 + b1 (fp32)
// 16 warps, each a 32x32 output tile per weight.
// ---------------------------------------------------------------------------
template<bool GATHER>
__global__ __launch_bounds__(GT, 1)
void gemm_fused(const float* __restrict__ A, const int* __restrict__ gidx,
                int w0i, int w1i,
                const float* __restrict__ b0, const float* __restrict__ b1,
                __half* __restrict__ m_out, float* __restrict__ self_out,
                int nrows)
{
    extern __shared__ float smem[];
    float* As  = smem;
    float* Wp0 = smem + WORDS;
    float* Wp1 = smem + 2 * WORDS;

    const int tid  = threadIdx.x;
    const int row0 = blockIdx.x * BM;

    {   // copy pre-permuted weights (4112 float4 each)
        const float4* s0 = (const float4*)g_wp[w0i];
        const float4* s1 = (const float4*)g_wp[w1i];
        float4* d0 = (float4*)Wp0;
        float4* d1 = (float4*)Wp1;
        #pragma unroll
        for (int i = 0; i < 9; i++) {
            int idx = i * GT + tid;
            if (idx < WORDS / 4) { d0[idx] = s0[idx]; d1[idx] = s1[idx]; }
        }
    }
    stage_A<GATHER>(A, gidx, row0, nrows, As);
    __syncthreads();

    const int lane = tid & 31, wid = tid >> 5;
    const int wn = wid & 3;          // 4 col groups of 32
    const int wm = wid >> 2;         // 4 row groups of 32
    const int g = lane >> 2, tg = lane & 3;
    const int R = wm * 32;

    float acc0[2][4][4], acc1[2][4][4];
    #pragma unroll
    for (int mt = 0; mt < 2; mt++)
        #pragma unroll
        for (int nt = 0; nt < 4; nt++)
            #pragma unroll
            for (int i = 0; i < 4; i++) { acc0[mt][nt][i] = 0.f; acc1[mt][nt][i] = 0.f; }

    #pragma unroll
    for (int ks = 0; ks < 16; ks++) {
        const float* as = As + ks * SLICE;
        float2 afA[2], afB[2];
        #pragma unroll
        for (int mt = 0; mt < 2; mt++) {
            int r = R + mt * 16 + g;
            afA[mt] = *(const float2*)(as + r * 8 + tg * 2);
            afB[mt] = *(const float2*)(as + (r + 8) * 8 + tg * 2);
        }
        const float* ws0 = Wp0 + ks * SLICE;
        const float* ws1 = Wp1 + ks * SLICE;
        #pragma unroll
        for (int nt = 0; nt < 4; nt++) {
            int cw = (wn * 32 + nt * 8 + g) * 8 + tg * 2;
            float2 bf0 = *(const float2*)(ws0 + cw);
            float2 bf1 = *(const float2*)(ws1 + cw);
            #pragma unroll
            for (int mt = 0; mt < 2; mt++) {
                mma_tf32(acc0[mt][nt],
                         __float_as_uint(afA[mt].x), __float_as_uint(afB[mt].x),
                         __float_as_uint(afA[mt].y), __float_as_uint(afB[mt].y),
                         __float_as_uint(bf0.x), __float_as_uint(bf0.y));
                mma_tf32(acc1[mt][nt],
                         __float_as_uint(afA[mt].x), __float_as_uint(afB[mt].x),
                         __float_as_uint(afA[mt].y), __float_as_uint(afB[mt].y),
                         __float_as_uint(bf1.x), __float_as_uint(bf1.y));
            }
        }
    }

    float2 bv0[4], bv1[4];
    #pragma unroll
    for (int nt = 0; nt < 4; nt++) {
        int col = wn * 32 + nt * 8 + 2 * tg;
        bv0[nt] = *(const float2*)(b0 + col);
        bv1[nt] = *(const float2*)(b1 + col);
    }

    #pragma unroll
    for (int mt = 0; mt < 2; mt++) {
        #pragma unroll
        for (int hh = 0; hh < 2; hh++) {
            int grow = row0 + R + mt * 16 + g + hh * 8;
            if (grow >= nrows) continue;
            #pragma unroll
            for (int nt = 0; nt < 4; nt++) {
                int col = wn * 32 + nt * 8 + 2 * tg;
                float mx = fmaxf(acc0[mt][nt][hh*2+0] + bv0[nt].x, 0.f);
                float my = fmaxf(acc0[mt][nt][hh*2+1] + bv0[nt].y, 0.f);
                *(__half2*)(m_out + (size_t)grow * HD + col) =
                    __floats2half2_rn(mx, my);
                float2 s;
                s.x = acc1[mt][nt][hh*2+0] + bv1[nt].x;
                s.y = acc1[mt][nt][hh*2+1] + bv1[nt].y;
                *(float2*)(self_out + (size_t)grow * HD + col) = s;
            }
        }
    }
}

// ---------------------------------------------------------------------------
// Accumulate GEMM: out += A @ W   (16 warps, 32x32 per warp)
// ---------------------------------------------------------------------------
__global__ __launch_bounds__(GT, 1)
void gemm_acc(const float* __restrict__ A, int wi, float* __restrict__ out,
              int nrows)
{
    extern __shared__ float smem[];
    float* As = smem;
    float* Wp = smem + WORDS;

    const int tid  = threadIdx.x;
    const int row0 = blockIdx.x * BM;

    {
        const float4* s = (const float4*)g_wp[wi];
        float4* d = (float4*)Wp;
        #pragma unroll
        for (int i = 0; i < 9; i++) {
            int idx = i * GT + tid;
            if (idx < WORDS / 4) d[idx] = s[idx];
        }
    }
    stage_A<false>(A, nullptr, row0, nrows, As);
    __syncthreads();

    const int lane = tid & 31, wid = tid >> 5;
    const int wn = wid & 3;
    const int wm = wid >> 2;
    const int g = lane >> 2, tg = lane & 3;
    const int R = wm * 32;

    float acc[2][4][4];
    #pragma unroll
    for (int mt = 0; mt < 2; mt++)
        #pragma unroll
        for (int nt = 0; nt < 4; nt++)
            #pragma unroll
            for (int i = 0; i < 4; i++) acc[mt][nt][i] = 0.f;

    #pragma unroll
    for (int ks = 0; ks < 16; ks++) {
        const float* as = As + ks * SLICE;
        float2 afA[2], afB[2];
        #pragma unroll
        for (int mt = 0; mt < 2; mt++) {
            int r = R + mt * 16 + g;
            afA[mt] = *(const float2*)(as + r * 8 + tg * 2);
            afB[mt] = *(const float2*)(as + (r + 8) * 8 + tg * 2);
        }
        const float* ws = Wp + ks * SLICE;
        #pragma unroll
        for (int nt = 0; nt < 4; nt++) {
            int cw = (wn * 32 + nt * 8 + g) * 8 + tg * 2;
            float2 bf = *(const float2*)(ws + cw);
            #pragma unroll
            for (int mt = 0; mt < 2; mt++)
                mma_tf32(acc[mt][nt],
                         __float_as_uint(afA[mt].x), __float_as_uint(afB[mt].x),
                         __float_as_uint(afA[mt].y), __float_as_uint(afB[mt].y),
                         __float_as_uint(bf.x), __float_as_uint(bf.y));
        }
    }

    #pragma unroll
    for (int mt = 0; mt < 2; mt++) {
        #pragma unroll
        for (int hh = 0; hh < 2; hh++) {
            int grow = row0 + R + mt * 16 + g + hh * 8;
            if (grow >= nrows) continue;
            #pragma unroll
            for (int nt = 0; nt < 4; nt++) {
                int col = wn * 32 + nt * 8 + 2 * tg;
                float2 p = *(const float2*)(out + (size_t)grow * HD + col);
                p.x += acc[mt][nt][hh*2+0];
                p.y += acc[mt][nt][hh*2+1];
                *(float2*)(out + (size_t)grow * HD + col) = p;
            }
        }
    }
}

// ---------------------------------------------------------------------------
__global__ void csr_offsets(const int* __restrict__ dst, int* __restrict__ rs,
                            int nE, int nN)
{
    int n = blockIdx.x * blockDim.x + threadIdx.x;
    if (n > nN) return;
    if (n == nN) { rs[n] = nE; return; }
    int lo = 0, hi = nE;
    while (lo < hi) {
        int mid = (lo + hi) >> 1;
        if (__ldg(&dst[mid]) < n) lo = mid + 1; else hi = mid;
    }
    rs[n] = lo;
}

// ---------------------------------------------------------------------------
// Segmented max over fp16 messages; software-pipelined x4 (MLP=4).
// ---------------------------------------------------------------------------
__global__ __launch_bounds__(256)
void seg_max_h(const __half* __restrict__ m, const int* __restrict__ src,
               const int* __restrict__ rs, float* __restrict__ agg, int nN)
{
    int warp = (blockIdx.x * blockDim.x + threadIdx.x) >> 5;
    int lane = threadIdx.x & 31;
    if (warp >= nN) return;

    int e0 = __ldg(&rs[warp]);
    int e1 = __ldg(&rs[warp + 1]);

    const __half2 z = __float2half2_rn(0.f);
    __half2 a0 = z, a1 = z;
    const uint2* m2 = (const uint2*)m;

    for (int eb = e0; eb < e1; eb += 32) {
        int cnt = min(32, e1 - eb);
        int s_l = (lane < cnt) ? __ldg(&src[eb + lane]) : 0;
        int i = 0;
        #pragma unroll 1
        for (; i + 4 <= cnt; i += 4) {
            int s0 = __shfl_sync(0xffffffffu, s_l, i);
            int s1 = __shfl_sync(0xffffffffu, s_l, i + 1);
            int s2 = __shfl_sync(0xffffffffu, s_l, i + 2);
            int s3 = __shfl_sync(0xffffffffu, s_l, i + 3);
            uint2 v0 = __ldg(&m2[(size_t)s0 * 32 + lane]);
            uint2 v1 = __ldg(&m2[(size_t)s1 * 32 + lane]);
            uint2 v2 = __ldg(&m2[(size_t)s2 * 32 + lane]);
            uint2 v3 = __ldg(&m2[(size_t)s3 * 32 + lane]);
            __half2 t0 = __hmax2(*(__half2*)&v0.x, *(__half2*)&v1.x);
            __half2 t1 = __hmax2(*(__half2*)&v2.x, *(__half2*)&v3.x);
            a0 = __hmax2(a0, __hmax2(t0, t1));
            __half2 u0 = __hmax2(*(__half2*)&v0.y, *(__half2*)&v1.y);
            __half2 u1 = __hmax2(*(__half2*)&v2.y, *(__half2*)&v3.y);
            a1 = __hmax2(a1, __hmax2(u0, u1));
        }
        #pragma unroll 1
        for (; i < cnt; i++) {
            int s = __shfl_sync(0xffffffffu, s_l, i);
            uint2 v = __ldg(&m2[(size_t)s * 32 + lane]);
            a0 = __hmax2(a0, *(__half2*)&v.x);
            a1 = __hmax2(a1, *(__half2*)&v.y);
        }
    }
    float2 f0 = __half22float2(a0);
    float2 f1 = __half22float2(a1);
    float4 o = make_float4(f0.x, f0.y, f1.x, f1.y);
    ((float4*)agg)[(size_t)warp * 32 + lane] = o;
}

// ---------------------------------------------------------------------------
extern "C" void kernel_launch(void* const* d_in, const int* in_sizes, int n_in,
                              void* d_out, int out_size)
{
    const int*   node_ids = (const int*)  d_in[0];
    const int*   src      = (const int*)  d_in[1];
    const int*   dst      = (const int*)  d_in[2];
    const float* emb      = (const float*)d_in[3];
    const float* W_pool1  = (const float*)d_in[4];
    const float* b_pool1  = (const float*)d_in[5];
    const float* W_self1  = (const float*)d_in[6];
    const float* W_neigh1 = (const float*)d_in[7];
    const float* b1       = (const float*)d_in[8];
    const float* W_pool2  = (const float*)d_in[9];
    const float* b_pool2  = (const float*)d_in[10];
    const float* W_self2  = (const float*)d_in[11];
    const float* W_neigh2 = (const float*)d_in[12];
    const float* b2       = (const float*)d_in[13];
    float*       out      = (float*)d_out;

    const int nN = in_sizes[0];
    const int nE = in_sizes[1];

    __half* mh;  float *agg, *h1;  int *rs;
    cudaGetSymbolAddress((void**)&mh,  g_mh);
    cudaGetSymbolAddress((void**)&agg, g_agg);
    cudaGetSymbolAddress((void**)&h1,  g_h1);
    cudaGetSymbolAddress((void**)&rs,  g_rs);

    const int SMEM3 = 3 * WORDS * (int)sizeof(float);   // 197376
    const int SMEM2 = 2 * WORDS * (int)sizeof(float);   // 131584

    cudaFuncSetAttribute(gemm_fused<true >, cudaFuncAttributeMaxDynamicSharedMemorySize, SMEM3);
    cudaFuncSetAttribute(gemm_fused<false>, cudaFuncAttributeMaxDynamicSharedMemorySize, SMEM3);
    cudaFuncSetAttribute(gemm_acc,          cudaFuncAttributeMaxDynamicSharedMemorySize, SMEM2);

    const int gemm_blocks = (nN + BM - 1) / BM;
    const int csr_blocks  = (nN + 1 + 255) / 256;
    const int seg_blocks  = (nN + 7) / 8;

    prep_w<<<dim3(32, 6), 256>>>(W_pool1, W_self1, W_neigh1, W_pool2, W_self2, W_neigh2);
    csr_offsets<<<csr_blocks, 256>>>(dst, rs, nE, nN);

    // ---- Layer 1 ----
    gemm_fused<true><<<gemm_blocks, GT, SMEM3>>>(
        emb, node_ids, 0, 1, b_pool1, b1, mh, h1, nN);
    seg_max_h<<<seg_blocks, 256>>>(mh, src, rs, agg, nN);
    gemm_acc<<<gemm_blocks, GT, SMEM2>>>(agg, 2, h1, nN);

    // ---- Layer 2 ----
    gemm_fused<false><<<gemm_blocks, GT, SMEM3>>>(
        h1, nullptr, 3, 4, b_pool2, b2, mh, out, nN);
    seg_max_h<<<seg_blocks, 256>>>(mh, src, rs, agg, nN);
    gemm_acc<<<gemm_blocks, GT, SMEM2>>>(agg, 5, out, nN);
}